// round 3
// baseline (speedup 1.0000x reference)
#include <cuda_runtime.h>
#include <cstdint>

#define BB 8
#define CC 128
#define HH 160
#define WW 512
#define DMAX 64

#define TJ_BLK 128
#define KC2 16      // channel pairs per chunk (32 channels)
#define NCHUNK 4
#define SLS 129     // float2 per sL row (128 + 1 pad)
#define SRS 193     // float2 per sR row (192 + 1 pad)

__device__ __forceinline__ uint32_t swz(uint32_t col) {
    return col ^ ((col >> 3) & 0xFu);
}
__device__ __forceinline__ void ffma2(unsigned long long& d, unsigned long long a,
                                      unsigned long long b) {
    asm("fma.rn.f32x2 %0, %1, %2, %0;" : "+l"(d) : "l"(a), "l"(b));
}

__global__ __launch_bounds__(128, 2)
void cost_volume_kernel(const float* __restrict__ left,
                        const float* __restrict__ right,
                        float* __restrict__ out) {
    __shared__ float2 sL[KC2][SLS];   // 16512 B: pair-interleaved left tile
    __shared__ float2 sR[KC2][SRS];   // 24704 B: pair-interleaved right window

    const int tid = threadIdx.x;
    const int j0B = blockIdx.x * TJ_BLK;
    const int h   = blockIdx.y;
    const int b   = blockIdx.z;

    // compute-phase map: td selects 8 disparities, tj selects 8 j's
    const int td = tid & 7;
    const int tj = tid >> 3;

    const size_t plane = (size_t)HH * WW;
    const float* Lbase = left  + ((size_t)b * CC * HH + h) * WW;
    const float* Rbase = right + ((size_t)b * CC * HH + h) * WW;

    // precomputed swizzled element indices
    uint32_t lI[8];
    #pragma unroll
    for (int jj = 0; jj < 8; jj++) lI[jj] = swz((uint32_t)(tj * 8 + jj));
    uint32_t rI[15];
    const int rb = tj * 8 - td * 8 + 57;   // window col = j - d + 64 - j0B, minus 7..0
    #pragma unroll
    for (int s = 0; s < 15; s++) rI[s] = swz((uint32_t)(rb + s));

    // accumulators: f32x2 packed over channel pairs
    unsigned long long acc[8][8];
    #pragma unroll
    for (int dd = 0; dd < 8; dd++)
        #pragma unroll
        for (int jj = 0; jj < 8; jj++) acc[dd][jj] = 0ull;

    for (int chunk = 0; chunk < NCHUNK; chunk++) {
        __syncthreads();   // prior compute reads done before overwrite

        // ---- load L tile: 512 pair-items (c2 in [0,16), grp in [0,32)) ----
        #pragma unroll
        for (int it = 0; it < 4; it++) {
            const int idx = it * 128 + tid;
            const int c2  = idx >> 5;
            const int grp = idx & 31;
            const float* p0 = Lbase + (size_t)(chunk * 32 + 2 * c2) * plane + j0B + grp * 4;
            const float4 a = *reinterpret_cast<const float4*>(p0);
            const float4 bq = *reinterpret_cast<const float4*>(p0 + plane);
            sL[c2][swz((uint32_t)(grp * 4 + 0))] = make_float2(a.x, bq.x);
            sL[c2][swz((uint32_t)(grp * 4 + 1))] = make_float2(a.y, bq.y);
            sL[c2][swz((uint32_t)(grp * 4 + 2))] = make_float2(a.z, bq.z);
            sL[c2][swz((uint32_t)(grp * 4 + 3))] = make_float2(a.w, bq.w);
        }

        // ---- load R window: 768 pair-items (c2 in [0,16), grp in [0,48)) ----
        #pragma unroll
        for (int it = 0; it < 6; it++) {
            const int idx = it * 128 + tid;
            const int c2  = idx / 48;
            const int grp = idx - c2 * 48;
            const int gj0 = j0B - 64 + grp * 4;          // global j of window col grp*4
            float4 a, bq;
            if (gj0 >= 0) {
                const float* p0 = Rbase + (size_t)(chunk * 32 + 2 * c2) * plane + gj0;
                a  = *reinterpret_cast<const float4*>(p0);
                bq = *reinterpret_cast<const float4*>(p0 + plane);
            } else {
                // only feeds masked (j < d) outputs
                a  = make_float4(0.f, 0.f, 0.f, 0.f);
                bq = a;
            }
            sR[c2][swz((uint32_t)(grp * 4 + 0))] = make_float2(a.x, bq.x);
            sR[c2][swz((uint32_t)(grp * 4 + 1))] = make_float2(a.y, bq.y);
            sR[c2][swz((uint32_t)(grp * 4 + 2))] = make_float2(a.z, bq.z);
            sR[c2][swz((uint32_t)(grp * 4 + 3))] = make_float2(a.w, bq.w);
        }

        __syncthreads();

        // ---- compute: 16 channel pairs x (8 d x 8 j) FFMA2 ----
        #pragma unroll
        for (int c2 = 0; c2 < KC2; c2++) {
            unsigned long long lv[8], rv[15];
            #pragma unroll
            for (int jj = 0; jj < 8; jj++)
                lv[jj] = *reinterpret_cast<const unsigned long long*>(&sL[c2][lI[jj]]);
            #pragma unroll
            for (int s = 0; s < 15; s++)
                rv[s] = *reinterpret_cast<const unsigned long long*>(&sR[c2][rI[s]]);
            #pragma unroll
            for (int dd = 0; dd < 8; dd++)
                #pragma unroll
                for (int jj = 0; jj < 8; jj++)
                    ffma2(acc[dd][jj], lv[jj], rv[jj - dd + 7]);
        }
    }

    // ---- epilogue: reduce pair, scale 1/C, mask j<d, float4 stores ----
    const float inv = 1.0f / (float)CC;
    float* obase = out + ((size_t)b * DMAX * HH + h) * WW;
    #pragma unroll
    for (int dd = 0; dd < 8; dd++) {
        const int d = td * 8 + dd;
        float* orow = obase + (size_t)d * plane + j0B + tj * 8;
        #pragma unroll
        for (int q = 0; q < 2; q++) {
            float vals[4];
            #pragma unroll
            for (int i = 0; i < 4; i++) {
                const int jj = q * 4 + i;
                union { unsigned long long u; float2 f2; } cv;
                cv.u = acc[dd][jj];
                const float f = (cv.f2.x + cv.f2.y) * inv;
                const int j = j0B + tj * 8 + jj;
                vals[i] = (j >= d) ? f : 0.0f;
            }
            float4 o;
            o.x = vals[0]; o.y = vals[1]; o.z = vals[2]; o.w = vals[3];
            *reinterpret_cast<float4*>(orow + q * 4) = o;
        }
    }
}

extern "C" void kernel_launch(void* const* d_in, const int* in_sizes, int n_in,
                              void* d_out, int out_size) {
    const float* left  = (const float*)d_in[0];
    const float* right = (const float*)d_in[1];
    float* out = (float*)d_out;

    dim3 grid(WW / TJ_BLK, HH, BB);
    cost_volume_kernel<<<grid, 128>>>(left, right, out);
}